// round 2
// baseline (speedup 1.0000x reference)
#include <cuda_runtime.h>
#include <math.h>

// Problem constants
#define BB 4
#define HH 4
#define LL 2048
#define DD 1024
#define HD 256
#define ROWS (BB*LL)     // 8192
#define BHN  (BB*HH)     // 16

// ---------------- scratch (device globals; no allocations allowed) ----------
__device__ float g_xn [(size_t)ROWS * DD];        // 32 MB  normalized x
__device__ float g_qkv[(size_t)ROWS * 3 * DD];    // 96 MB  qkv projection
__device__ float g_q  [(size_t)BHN * LL * HD];    // 32 MB
__device__ float g_k  [(size_t)BHN * LL * HD];    // 32 MB
__device__ float g_v  [(size_t)BHN * LL * HD];    // 32 MB
__device__ float g_ao [(size_t)ROWS * DD];        // 32 MB  attention output [B,L,D]

// ---------------- RMSNorm ---------------------------------------------------
__global__ void rmsnorm_kernel(const float* __restrict__ x,
                               const float* __restrict__ w)
{
    const int row = blockIdx.x;
    const int t = threadIdx.x;               // 256 threads, one float4 each
    const float4 v = ((const float4*)(x + (size_t)row * DD))[t];
    float ss = v.x*v.x + v.y*v.y + v.z*v.z + v.w*v.w;
    #pragma unroll
    for (int o = 16; o; o >>= 1) ss += __shfl_xor_sync(0xffffffffu, ss, o);
    __shared__ float swarp[8];
    __shared__ float s_r;
    if ((t & 31) == 0) swarp[t >> 5] = ss;
    __syncthreads();
    if (t < 8) {
        float tot = swarp[t];
        #pragma unroll
        for (int o = 4; o; o >>= 1) tot += __shfl_xor_sync(0xffu, tot, o);
        if (t == 0) s_r = rsqrtf(tot * (1.0f / DD) + 1e-6f);
    }
    __syncthreads();
    const float r = s_r;
    const float4 wv = ((const float4*)w)[t];
    float4 o4;
    o4.x = v.x * r * wv.x; o4.y = v.y * r * wv.y;
    o4.z = v.z * r * wv.z; o4.w = v.w * r * wv.w;
    ((float4*)(g_xn + (size_t)row * DD))[t] = o4;
}

// ---------------- SGEMM: C[M,N] = A[M,K] @ B[N,K]^T (row-major) -------------
// 128x128 tile, BK=8, 256 threads, 8x8 per-thread microtile.
// EPI: C = res + (*rsp) * acc  (fused residual epilogue for out-proj)
template<bool EPI>
__global__ void __launch_bounds__(256)
sgemm_nt(const float* __restrict__ A, const float* __restrict__ Bm,
         float* __restrict__ C, int M, int N, int K,
         const float* __restrict__ res, const float* __restrict__ rsp)
{
    __shared__ float As[8][128];
    __shared__ float Bs[8][128];
    const int tid  = threadIdx.x;
    const int lrow = tid >> 1;
    const int lcol = (tid & 1) << 2;
    const int tx   = tid & 15;
    const int ty   = tid >> 4;
    const float* Ab = A  + (size_t)(blockIdx.y * 128) * K;
    const float* Bb = Bm + (size_t)(blockIdx.x * 128) * K;

    float acc[8][8];
    #pragma unroll
    for (int i = 0; i < 8; i++)
        #pragma unroll
        for (int j = 0; j < 8; j++) acc[i][j] = 0.f;

    for (int k0 = 0; k0 < K; k0 += 8) {
        float4 a = *(const float4*)(Ab + (size_t)lrow * K + (k0 + lcol));
        float4 b = *(const float4*)(Bb + (size_t)lrow * K + (k0 + lcol));
        As[lcol+0][lrow] = a.x; As[lcol+1][lrow] = a.y;
        As[lcol+2][lrow] = a.z; As[lcol+3][lrow] = a.w;
        Bs[lcol+0][lrow] = b.x; Bs[lcol+1][lrow] = b.y;
        Bs[lcol+2][lrow] = b.z; Bs[lcol+3][lrow] = b.w;
        __syncthreads();
        #pragma unroll
        for (int kk = 0; kk < 8; kk++) {
            float ar[8], br[8];
            *(float4*)&ar[0] = *(const float4*)&As[kk][ty*8];
            *(float4*)&ar[4] = *(const float4*)&As[kk][ty*8 + 4];
            *(float4*)&br[0] = *(const float4*)&Bs[kk][tx*8];
            *(float4*)&br[4] = *(const float4*)&Bs[kk][tx*8 + 4];
            #pragma unroll
            for (int i = 0; i < 8; i++)
                #pragma unroll
                for (int j = 0; j < 8; j++)
                    acc[i][j] = fmaf(ar[i], br[j], acc[i][j]);
        }
        __syncthreads();
    }

    const int row0 = blockIdx.y * 128 + ty * 8;
    const int col0 = blockIdx.x * 128 + tx * 8;
    float s = 0.f;
    if (EPI) s = *rsp;
    #pragma unroll
    for (int i = 0; i < 8; i++) {
        float* cp = C + (size_t)(row0 + i) * N + col0;
        if (EPI) {
            const float* rp = res + (size_t)(row0 + i) * N + col0;
            #pragma unroll
            for (int jj = 0; jj < 2; jj++) {
                float4 r4 = *(const float4*)(rp + jj * 4);
                float4 w;
                w.x = fmaf(s, acc[i][jj*4+0], r4.x);
                w.y = fmaf(s, acc[i][jj*4+1], r4.y);
                w.z = fmaf(s, acc[i][jj*4+2], r4.z);
                w.w = fmaf(s, acc[i][jj*4+3], r4.w);
                *(float4*)(cp + jj * 4) = w;
            }
        } else {
            #pragma unroll
            for (int jj = 0; jj < 2; jj++) {
                float4 w;
                w.x = acc[i][jj*4+0]; w.y = acc[i][jj*4+1];
                w.z = acc[i][jj*4+2]; w.w = acc[i][jj*4+3];
                *(float4*)(cp + jj * 4) = w;
            }
        }
    }
}

// ---------------- RoPE + scatter qkv -> q/k/v in [B,H,L,hd] -----------------
// One thread per (row, which, head, pair) -> handles elements dp and dp+128.
__global__ void rope_scatter_kernel()
{
    const int t  = blockIdx.x * 256 + threadIdx.x;  // < 8192*1536
    const int bl = t / 1536;
    const int r  = t - bl * 1536;
    const int w  = r >> 9;          // 0=q,1=k,2=v
    const int h  = (r >> 7) & 3;
    const int dp = r & 127;
    const float* src = g_qkv + (size_t)bl * 3072 + w * 1024 + h * 256 + dp;
    const float x0 = src[0];
    const float x1 = src[128];
    const int b = bl >> 11;
    const int l = bl & 2047;
    float* base = (w == 0) ? g_q : (w == 1) ? g_k : g_v;
    float* dst = base + ((size_t)(b * HH + h) * LL + l) * HD + dp;
    if (w < 2) {
        const float invf = powf(10000.0f, -(float)dp * (1.0f / 128.0f));
        const float ang  = (float)l * invf;
        const float c = cosf(ang), s = sinf(ang);
        dst[0]   = x0 * c - x1 * s;
        dst[128] = x1 * c + x0 * s;
    } else {
        dst[0]   = x0;
        dst[128] = x1;
    }
}

// ---------------- Flash attention (fp32, online softmax) --------------------
// CTA = (q-tile of 64 rows) x (b*H+h). 256 threads. K/V tiles of 64 keys.
#define FQS 260   // padded row stride for Q/K/V tiles (bank-friendly)
#define FPS 68    // padded row stride for P tile
#define FLASH_SMEM_FLOATS (64*FQS*2 + 64*FPS + 192)
#define FLASH_SMEM_BYTES  (FLASH_SMEM_FLOATS * 4)

__global__ void __launch_bounds__(256) flash_kernel()
{
    extern __shared__ float sm[];
    float* Qs  = sm;                 // [64][FQS]
    float* KVs = Qs  + 64 * FQS;     // [64][FQS], K then V
    float* Ps  = KVs + 64 * FQS;     // [64][FPS]
    float* s_m = Ps  + 64 * FPS;     // [64]
    float* s_l = s_m + 64;           // [64]
    float* s_a = s_l + 64;           // [64]

    const int tid = threadIdx.x;
    const int tx  = tid & 15;        // 4-col groups (x4 in hd via cc stripes)
    const int ty  = tid >> 4;        // 4-row groups
    const int bh  = blockIdx.y;
    const int q0  = blockIdx.x * 64;

    const float* Qg = g_q + ((size_t)bh * LL + q0) * HD;
    const float* Kg = g_k + (size_t)bh * LL * HD;
    const float* Vg = g_v + (size_t)bh * LL * HD;

    #pragma unroll
    for (int it = 0; it < 16; it++) {
        int idx = tid + it * 256;            // 0..4095 float4 slots
        int rr = idx >> 6, c4 = idx & 63;
        *(float4*)&Qs[rr * FQS + c4 * 4] = ((const float4*)Qg)[idx];
    }
    if (tid < 64) { s_m[tid] = -1e30f; s_l[tid] = 0.f; }

    float o[4][16];
    #pragma unroll
    for (int i = 0; i < 4; i++)
        #pragma unroll
        for (int c = 0; c < 16; c++) o[i][c] = 0.f;

    for (int kt = 0; kt < 32; kt++) {
        // --- load K tile ---
        const float4* Kt = (const float4*)(Kg + (size_t)kt * 64 * HD);
        #pragma unroll
        for (int it = 0; it < 16; it++) {
            int idx = tid + it * 256;
            int rr = idx >> 6, c4 = idx & 63;
            *(float4*)&KVs[rr * FQS + c4 * 4] = Kt[idx];
        }
        __syncthreads();

        // --- S = Q K^T (4x4 per thread) ---
        float sacc[4][4];
        #pragma unroll
        for (int i = 0; i < 4; i++)
            #pragma unroll
            for (int j = 0; j < 4; j++) sacc[i][j] = 0.f;
        #pragma unroll 2
        for (int k0 = 0; k0 < HD; k0 += 4) {
            float4 qv[4], kv[4];
            #pragma unroll
            for (int i = 0; i < 4; i++)
                qv[i] = *(const float4*)&Qs[(ty*4 + i) * FQS + k0];
            #pragma unroll
            for (int j = 0; j < 4; j++)
                kv[j] = *(const float4*)&KVs[(tx*4 + j) * FQS + k0];
            #pragma unroll
            for (int i = 0; i < 4; i++)
                #pragma unroll
                for (int j = 0; j < 4; j++) {
                    sacc[i][j] = fmaf(qv[i].x, kv[j].x, sacc[i][j]);
                    sacc[i][j] = fmaf(qv[i].y, kv[j].y, sacc[i][j]);
                    sacc[i][j] = fmaf(qv[i].z, kv[j].z, sacc[i][j]);
                    sacc[i][j] = fmaf(qv[i].w, kv[j].w, sacc[i][j]);
                }
        }
        #pragma unroll
        for (int i = 0; i < 4; i++)
            #pragma unroll
            for (int j = 0; j < 4; j++)
                Ps[(ty*4 + i) * FPS + tx*4 + j] = sacc[i][j] * 0.0625f;
        __syncthreads();

        // --- softmax per row (threads 0..63) ---
        if (tid < 64) {
            float* pr = Ps + tid * FPS;
            const float mold = s_m[tid];
            float mt = mold;
            #pragma unroll 8
            for (int j = 0; j < 64; j++) mt = fmaxf(mt, pr[j]);
            const float alpha = expf(mold - mt);
            float sum = 0.f;
            #pragma unroll 8
            for (int j = 0; j < 64; j++) {
                float p = expf(pr[j] - mt);
                pr[j] = p;
                sum += p;
            }
            s_l[tid] = s_l[tid] * alpha + sum;
            s_m[tid] = mt;
            s_a[tid] = alpha;
        }
        // --- load V tile (overlaps softmax; KVs reads finished at last sync) ---
        const float4* Vt = (const float4*)(Vg + (size_t)kt * 64 * HD);
        #pragma unroll
        for (int it = 0; it < 16; it++) {
            int idx = tid + it * 256;
            int rr = idx >> 6, c4 = idx & 63;
            *(float4*)&KVs[rr * FQS + c4 * 4] = Vt[idx];
        }
        __syncthreads();

        // --- rescale O, accumulate O += P V ---
        #pragma unroll
        for (int i = 0; i < 4; i++) {
            const float a = s_a[ty*4 + i];
            #pragma unroll
            for (int c = 0; c < 16; c++) o[i][c] *= a;
        }
        #pragma unroll 4
        for (int j = 0; j < 64; j++) {
            float pvr[4];
            #pragma unroll
            for (int i = 0; i < 4; i++) pvr[i] = Ps[(ty*4 + i) * FPS + j];
            #pragma unroll
            for (int cc = 0; cc < 4; cc++) {
                float4 v4 = *(const float4*)&KVs[j * FQS + cc*64 + tx*4];
                #pragma unroll
                for (int i = 0; i < 4; i++) {
                    o[i][cc*4+0] = fmaf(pvr[i], v4.x, o[i][cc*4+0]);
                    o[i][cc*4+1] = fmaf(pvr[i], v4.y, o[i][cc*4+1]);
                    o[i][cc*4+2] = fmaf(pvr[i], v4.z, o[i][cc*4+2]);
                    o[i][cc*4+3] = fmaf(pvr[i], v4.w, o[i][cc*4+3]);
                }
            }
        }
        __syncthreads();
    }

    // --- finalize: O /= l, write to g_ao in [B, L, H*hd] ---
    float linv[4];
    #pragma unroll
    for (int i = 0; i < 4; i++) linv[i] = 1.0f / s_l[ty*4 + i];
    const int b = bh >> 2, h = bh & 3;
    #pragma unroll
    for (int i = 0; i < 4; i++) {
        const int l = q0 + ty*4 + i;
        float* dst = g_ao + ((size_t)(b * LL + l)) * DD + h * HD;
        #pragma unroll
        for (int cc = 0; cc < 4; cc++) {
            float4 w;
            w.x = o[i][cc*4+0] * linv[i];
            w.y = o[i][cc*4+1] * linv[i];
            w.z = o[i][cc*4+2] * linv[i];
            w.w = o[i][cc*4+3] * linv[i];
            *(float4*)&dst[cc*64 + tx*4] = w;
        }
    }
}

// ---------------- launch -----------------------------------------------------
extern "C" void kernel_launch(void* const* d_in, const int* in_sizes, int n_in,
                              void* d_out, int out_size)
{
    const float* x      = (const float*)d_in[0];
    const float* norm_w = (const float*)d_in[1];
    const float* qkv_w  = (const float*)d_in[2];
    const float* out_w  = (const float*)d_in[3];
    const float* rsp    = (const float*)d_in[4];
    float* out = (float*)d_out;

    float *p_xn, *p_qkv, *p_ao;
    cudaGetSymbolAddress((void**)&p_xn,  g_xn);
    cudaGetSymbolAddress((void**)&p_qkv, g_qkv);
    cudaGetSymbolAddress((void**)&p_ao,  g_ao);

    cudaFuncSetAttribute(flash_kernel,
                         cudaFuncAttributeMaxDynamicSharedMemorySize,
                         FLASH_SMEM_BYTES);

    // 1. RMSNorm
    rmsnorm_kernel<<<ROWS, 256>>>(x, norm_w);
    // 2. QKV projection: [8192,3072] = xn @ qkv_w^T
    sgemm_nt<false><<<dim3((3 * DD) / 128, ROWS / 128), 256>>>(
        p_xn, qkv_w, p_qkv, ROWS, 3 * DD, DD, nullptr, nullptr);
    // 3. RoPE + scatter to [B,H,L,hd]
    rope_scatter_kernel<<<(ROWS * 1536) / 256, 256>>>();
    // 4. attention
    flash_kernel<<<dim3(LL / 64, BHN), 256, FLASH_SMEM_BYTES>>>();
    // 5. out projection + residual epilogue -> d_out
    sgemm_nt<true><<<dim3(DD / 128, ROWS / 128), 256>>>(
        p_ao, out_w, out, ROWS, DD, DD, x, rsp);
}

// round 11
// speedup vs baseline: 1.3740x; 1.3740x over previous
#include <cuda_runtime.h>
#include <cuda_bf16.h>
#include <math.h>
#include <stdint.h>

// Problem constants
#define BB 4
#define HH 4
#define LL 2048
#define DD 1024
#define HD 256
#define ROWS (BB*LL)     // 8192
#define BHN  (BB*HH)     // 16

// ---------------- scratch (device globals; no allocations allowed) ----------
__device__ __nv_bfloat16 g_xn_bf [(size_t)ROWS * DD];       // normalized x (bf16)
__device__ __nv_bfloat16 g_wqkv_bf[(size_t)3 * DD * DD];    // qkv_w in bf16
__device__ __nv_bfloat16 g_wout_bf[(size_t)DD * DD];        // out_w in bf16
__device__ float         g_qkv[(size_t)ROWS * 3 * DD];      // qkv projection (fp32)
__device__ float         g_q  [(size_t)BHN * LL * HD];
__device__ float         g_k  [(size_t)BHN * LL * HD];
__device__ float         g_v  [(size_t)BHN * LL * HD];
__device__ __nv_bfloat16 g_ao_bf[(size_t)ROWS * DD];        // attention out (bf16)

// =====================  helpers  ============================================
__device__ __forceinline__ uint32_t smem_u32(const void* p) {
    uint32_t a;
    asm("{ .reg .u64 t; cvta.to.shared.u64 t, %1; cvt.u32.u64 %0, t; }"
        : "=r"(a) : "l"(p));
    return a;
}
__device__ __forceinline__ void ldmx4(uint32_t addr, uint32_t& r0, uint32_t& r1,
                                      uint32_t& r2, uint32_t& r3) {
    asm volatile("ldmatrix.sync.aligned.m8n8.x4.shared.b16 {%0,%1,%2,%3}, [%4];"
                 : "=r"(r0), "=r"(r1), "=r"(r2), "=r"(r3) : "r"(addr));
}
__device__ __forceinline__ void mma16816(float* d, const uint32_t* a,
                                         uint32_t b0, uint32_t b1) {
    asm volatile(
        "mma.sync.aligned.m16n8k16.row.col.f32.bf16.bf16.f32 "
        "{%0,%1,%2,%3}, {%4,%5,%6,%7}, {%8,%9}, {%0,%1,%2,%3};"
        : "+f"(d[0]), "+f"(d[1]), "+f"(d[2]), "+f"(d[3])
        : "r"(a[0]), "r"(a[1]), "r"(a[2]), "r"(a[3]), "r"(b0), "r"(b1));
}
__device__ __forceinline__ void cp16(uint32_t dst, const void* src) {
    asm volatile("cp.async.cg.shared.global [%0], [%1], 16;"
                 :: "r"(dst), "l"(__cvta_generic_to_global(src)));
}
#define CP_COMMIT() asm volatile("cp.async.commit_group;")
#define CP_WAIT(n)  asm volatile("cp.async.wait_group %0;" :: "n"(n))

// ---------------- fp32 -> bf16 convert (weights) ----------------------------
__global__ void f2bf_kernel(const float* __restrict__ src,
                            __nv_bfloat16* __restrict__ dst, int n4)
{
    int i = blockIdx.x * 256 + threadIdx.x;
    if (i < n4) {
        float4 v = ((const float4*)src)[i];
        __nv_bfloat162 h0 = __floats2bfloat162_rn(v.x, v.y);
        __nv_bfloat162 h1 = __floats2bfloat162_rn(v.z, v.w);
        uint2 w;
        w.x = *(uint32_t*)&h0; w.y = *(uint32_t*)&h1;
        ((uint2*)dst)[i] = w;
    }
}

// ---------------- RMSNorm (fp32 in -> bf16 out) ------------------------------
__global__ void rmsnorm_kernel(const float* __restrict__ x,
                               const float* __restrict__ w)
{
    const int row = blockIdx.x;
    const int t = threadIdx.x;
    const float4 v = ((const float4*)(x + (size_t)row * DD))[t];
    float ss = v.x*v.x + v.y*v.y + v.z*v.z + v.w*v.w;
    #pragma unroll
    for (int o = 16; o; o >>= 1) ss += __shfl_xor_sync(0xffffffffu, ss, o);
    __shared__ float swarp[8];
    __shared__ float s_r;
    if ((t & 31) == 0) swarp[t >> 5] = ss;
    __syncthreads();
    if (t < 8) {
        float tot = swarp[t];
        #pragma unroll
        for (int o = 4; o; o >>= 1) tot += __shfl_xor_sync(0xffu, tot, o);
        if (t == 0) s_r = rsqrtf(tot * (1.0f / DD) + 1e-6f);
    }
    __syncthreads();
    const float r = s_r;
    const float4 wv = ((const float4*)w)[t];
    __nv_bfloat162 h0 = __floats2bfloat162_rn(v.x * r * wv.x, v.y * r * wv.y);
    __nv_bfloat162 h1 = __floats2bfloat162_rn(v.z * r * wv.z, v.w * r * wv.w);
    uint2 o2;
    o2.x = *(uint32_t*)&h0; o2.y = *(uint32_t*)&h1;
    ((uint2*)(g_xn_bf + (size_t)row * DD))[t] = o2;
}

// ============ mma.sync bf16 GEMM:  C[M,N] = A[M,K] @ B[N,K]^T  ==============
// CTA tile 128x128, K-chunk 32, 8 warps (warp tile 64x32), cp.async double buf.
// smem rows padded to 40 bf16 (80B) -> conflict-free ldmatrix (gcd(80,128)=16).
#define TPAD 40                      // bf16 per smem row
#define TILE_B (128 * TPAD * 2)      // 10240 bytes per operand tile

template<bool EPI>
__global__ void __launch_bounds__(256) gemm_mma(
    const __nv_bfloat16* __restrict__ A, const __nv_bfloat16* __restrict__ Bm,
    float* __restrict__ C, int N, int K,
    const float* __restrict__ res, const float* __restrict__ rsp)
{
    __shared__ __align__(16) char smem[2 * 2 * TILE_B];   // [buf][A|B]
    const uint32_t s0 = smem_u32(smem);
    const int tid  = threadIdx.x;
    const int lane = tid & 31, wid = tid >> 5;
    const int tM = blockIdx.y * 128, tN = blockIdx.x * 128;
    const int wm = (wid & 1) * 64, wn = (wid >> 1) * 32;

    const __nv_bfloat16* Ag = A  + (size_t)tM * K;
    const __nv_bfloat16* Bg = Bm + (size_t)tN * K;

    float acc[16][4];
    #pragma unroll
    for (int i = 0; i < 16; i++)
        #pragma unroll
        for (int j = 0; j < 4; j++) acc[i][j] = 0.f;

    // chunk loader: 128x32 bf16 per operand, 16B cp.async chunks
    auto load_chunk = [&](int kc, int buf) {
        const uint32_t bufb = s0 + buf * 2 * TILE_B;
        #pragma unroll
        for (int t = 0; t < 2; t++) {
            int idx = tid + t * 256;          // 0..511
            int row = idx >> 2, c = idx & 3;
            uint32_t off = row * (TPAD * 2) + c * 16;
            cp16(bufb + off,          Ag + (size_t)row * K + kc * 32 + c * 8);
            cp16(bufb + TILE_B + off, Bg + (size_t)row * K + kc * 32 + c * 8);
        }
        CP_COMMIT();
    };

    const int NKC = K / 32;
    load_chunk(0, 0);

    const uint32_t rowoff = (lane & 15) * (TPAD * 2);
    const uint32_t colhi  = (lane & 16);   // 0 or 16 bytes

    for (int kc = 0; kc < NKC; kc++) {
        const int cur = kc & 1;
        if (kc + 1 < NKC) { load_chunk(kc + 1, cur ^ 1); CP_WAIT(1); }
        else              { CP_WAIT(0); }
        __syncthreads();

        const uint32_t aT = s0 + cur * 2 * TILE_B + wm * (TPAD * 2);
        const uint32_t bT = s0 + cur * 2 * TILE_B + TILE_B + wn * (TPAD * 2);
        #pragma unroll
        for (int s = 0; s < 2; s++) {
            const uint32_t col = s * 32 + colhi;
            uint32_t br[2][4];
            #pragma unroll
            for (int bj = 0; bj < 2; bj++)
                ldmx4(bT + bj * 16 * (TPAD * 2) + rowoff + col,
                      br[bj][0], br[bj][1], br[bj][2], br[bj][3]);
            #pragma unroll
            for (int mi = 0; mi < 4; mi++) {
                uint32_t a[4];
                ldmx4(aT + mi * 16 * (TPAD * 2) + rowoff + col,
                      a[0], a[1], a[2], a[3]);
                #pragma unroll
                for (int ni = 0; ni < 4; ni++) {
                    const int jj = ni >> 1, p = ni & 1;
                    mma16816(acc[mi * 4 + ni], a, br[jj][p], br[jj][p + 2]);
                }
            }
        }
        __syncthreads();
    }

    // ---- epilogue ----
    const float s_res = EPI ? *rsp : 0.f;
    const int g = lane >> 2, q = lane & 3;
    #pragma unroll
    for (int mi = 0; mi < 4; mi++) {
        const int row0 = tM + wm + mi * 16 + g;
        #pragma unroll
        for (int ni = 0; ni < 4; ni++) {
            const int col = tN + wn + ni * 8 + q * 2;
            const float* ac = acc[mi * 4 + ni];
            #pragma unroll
            for (int h = 0; h < 2; h++) {        // h=0: row0, h=1: row0+8
                const size_t o = (size_t)(row0 + h * 8) * N + col;
                float2 w;
                if (EPI) {
                    float2 r2 = *(const float2*)(res + o);
                    w.x = fmaf(s_res, ac[h * 2 + 0], r2.x);
                    w.y = fmaf(s_res, ac[h * 2 + 1], r2.y);
                } else {
                    w.x = ac[h * 2 + 0];
                    w.y = ac[h * 2 + 1];
                }
                *(float2*)(C + o) = w;
            }
        }
    }
}

// ---------------- RoPE + scatter qkv -> q/k/v in [B,H,L,hd] -----------------
__global__ void rope_scatter_kernel()
{
    const int t  = blockIdx.x * 256 + threadIdx.x;
    const int bl = t / 1536;
    const int r  = t - bl * 1536;
    const int w  = r >> 9;          // 0=q,1=k,2=v
    const int h  = (r >> 7) & 3;
    const int dp = r & 127;
    const float* src = g_qkv + (size_t)bl * 3072 + w * 1024 + h * 256 + dp;
    const float x0 = src[0];
    const float x1 = src[128];
    const int b = bl >> 11;
    const int l = bl & 2047;
    float* base = (w == 0) ? g_q : (w == 1) ? g_k : g_v;
    float* dst = base + ((size_t)(b * HH + h) * LL + l) * HD + dp;
    if (w < 2) {
        const float invf = powf(10000.0f, -(float)dp * (1.0f / 128.0f));
        const float ang  = (float)l * invf;
        const float c = cosf(ang), s = sinf(ang);
        dst[0]   = x0 * c - x1 * s;
        dst[128] = x1 * c + x0 * s;
    } else {
        dst[0]   = x0;
        dst[128] = x1;
    }
}

// ---------------- Flash attention (fp32, online softmax) --------------------
#define FQS 260
#define FPS 68
#define FLASH_SMEM_FLOATS (64*FQS*2 + 64*FPS + 192)
#define FLASH_SMEM_BYTES  (FLASH_SMEM_FLOATS * 4)

__global__ void __launch_bounds__(256) flash_kernel()
{
    extern __shared__ float smf[];
    float* Qs  = smf;
    float* KVs = Qs  + 64 * FQS;
    float* Ps  = KVs + 64 * FQS;
    float* s_m = Ps  + 64 * FPS;
    float* s_l = s_m + 64;
    float* s_a = s_l + 64;

    const int tid = threadIdx.x;
    const int tx  = tid & 15;
    const int ty  = tid >> 4;
    const int bh  = blockIdx.y;
    const int q0  = blockIdx.x * 64;

    const float* Qg = g_q + ((size_t)bh * LL + q0) * HD;
    const float* Kg = g_k + (size_t)bh * LL * HD;
    const float* Vg = g_v + (size_t)bh * LL * HD;

    #pragma unroll
    for (int it = 0; it < 16; it++) {
        int idx = tid + it * 256;
        int rr = idx >> 6, c4 = idx & 63;
        *(float4*)&Qs[rr * FQS + c4 * 4] = ((const float4*)Qg)[idx];
    }
    if (tid < 64) { s_m[tid] = -1e30f; s_l[tid] = 0.f; }

    float o[4][16];
    #pragma unroll
    for (int i = 0; i < 4; i++)
        #pragma unroll
        for (int c = 0; c < 16; c++) o[i][c] = 0.f;

    for (int kt = 0; kt < 32; kt++) {
        const float4* Kt = (const float4*)(Kg + (size_t)kt * 64 * HD);
        #pragma unroll
        for (int it = 0; it < 16; it++) {
            int idx = tid + it * 256;
            int rr = idx >> 6, c4 = idx & 63;
            *(float4*)&KVs[rr * FQS + c4 * 4] = Kt[idx];
        }
        __syncthreads();

        float sacc[4][4];
        #pragma unroll
        for (int i = 0; i < 4; i++)
            #pragma unroll
            for (int j = 0; j < 4; j++) sacc[i][j] = 0.f;
        #pragma unroll 2
        for (int k0 = 0; k0 < HD; k0 += 4) {
            float4 qv[4], kv[4];
            #pragma unroll
            for (int i = 0; i < 4; i++)
                qv[i] = *(const float4*)&Qs[(ty*4 + i) * FQS + k0];
            #pragma unroll
            for (int j = 0; j < 4; j++)
                kv[j] = *(const float4*)&KVs[(tx*4 + j) * FQS + k0];
            #pragma unroll
            for (int i = 0; i < 4; i++)
                #pragma unroll
                for (int j = 0; j < 4; j++) {
                    sacc[i][j] = fmaf(qv[i].x, kv[j].x, sacc[i][j]);
                    sacc[i][j] = fmaf(qv[i].y, kv[j].y, sacc[i][j]);
                    sacc[i][j] = fmaf(qv[i].z, kv[j].z, sacc[i][j]);
                    sacc[i][j] = fmaf(qv[i].w, kv[j].w, sacc[i][j]);
                }
        }
        #pragma unroll
        for (int i = 0; i < 4; i++)
            #pragma unroll
            for (int j = 0; j < 4; j++)
                Ps[(ty*4 + i) * FPS + tx*4 + j] = sacc[i][j] * 0.0625f;
        __syncthreads();

        if (tid < 64) {
            float* pr = Ps + tid * FPS;
            const float mold = s_m[tid];
            float mt = mold;
            #pragma unroll 8
            for (int j = 0; j < 64; j++) mt = fmaxf(mt, pr[j]);
            const float alpha = expf(mold - mt);
            float sum = 0.f;
            #pragma unroll 8
            for (int j = 0; j < 64; j++) {
                float p = expf(pr[j] - mt);
                pr[j] = p;
                sum += p;
            }
            s_l[tid] = s_l[tid] * alpha + sum;
            s_m[tid] = mt;
            s_a[tid] = alpha;
        }
        const float4* Vt = (const float4*)(Vg + (size_t)kt * 64 * HD);
        #pragma unroll
        for (int it = 0; it < 16; it++) {
            int idx = tid + it * 256;
            int rr = idx >> 6, c4 = idx & 63;
            *(float4*)&KVs[rr * FQS + c4 * 4] = Vt[idx];
        }
        __syncthreads();

        #pragma unroll
        for (int i = 0; i < 4; i++) {
            const float a = s_a[ty*4 + i];
            #pragma unroll
            for (int c = 0; c < 16; c++) o[i][c] *= a;
        }
        #pragma unroll 4
        for (int j = 0; j < 64; j++) {
            float pvr[4];
            #pragma unroll
            for (int i = 0; i < 4; i++) pvr[i] = Ps[(ty*4 + i) * FPS + j];
            #pragma unroll
            for (int cc = 0; cc < 4; cc++) {
                float4 v4 = *(const float4*)&KVs[j * FQS + cc*64 + tx*4];
                #pragma unroll
                for (int i = 0; i < 4; i++) {
                    o[i][cc*4+0] = fmaf(pvr[i], v4.x, o[i][cc*4+0]);
                    o[i][cc*4+1] = fmaf(pvr[i], v4.y, o[i][cc*4+1]);
                    o[i][cc*4+2] = fmaf(pvr[i], v4.z, o[i][cc*4+2]);
                    o[i][cc*4+3] = fmaf(pvr[i], v4.w, o[i][cc*4+3]);
                }
            }
        }
        __syncthreads();
    }

    float linv[4];
    #pragma unroll
    for (int i = 0; i < 4; i++) linv[i] = 1.0f / s_l[ty*4 + i];
    const int b = bh >> 2, h = bh & 3;
    #pragma unroll
    for (int i = 0; i < 4; i++) {
        const int l = q0 + ty*4 + i;
        __nv_bfloat16* dst = g_ao_bf + ((size_t)(b * LL + l)) * DD + h * HD;
        #pragma unroll
        for (int cc = 0; cc < 4; cc++) {
            __nv_bfloat162 h0 = __floats2bfloat162_rn(o[i][cc*4+0] * linv[i],
                                                      o[i][cc*4+1] * linv[i]);
            __nv_bfloat162 h1 = __floats2bfloat162_rn(o[i][cc*4+2] * linv[i],
                                                      o[i][cc*4+3] * linv[i]);
            uint2 w;
            w.x = *(uint32_t*)&h0; w.y = *(uint32_t*)&h1;
            *(uint2*)&dst[cc*64 + tx*4] = w;
        }
    }
}

// ---------------- launch -----------------------------------------------------
extern "C" void kernel_launch(void* const* d_in, const int* in_sizes, int n_in,
                              void* d_out, int out_size)
{
    const float* x      = (const float*)d_in[0];
    const float* norm_w = (const float*)d_in[1];
    const float* qkv_w  = (const float*)d_in[2];
    const float* out_w  = (const float*)d_in[3];
    const float* rsp    = (const float*)d_in[4];
    float* out = (float*)d_out;

    __nv_bfloat16 *p_xn, *p_wqkv, *p_wout, *p_ao;
    float *p_qkv;
    cudaGetSymbolAddress((void**)&p_xn,   g_xn_bf);
    cudaGetSymbolAddress((void**)&p_wqkv, g_wqkv_bf);
    cudaGetSymbolAddress((void**)&p_wout, g_wout_bf);
    cudaGetSymbolAddress((void**)&p_qkv,  g_qkv);
    cudaGetSymbolAddress((void**)&p_ao,   g_ao_bf);

    cudaFuncSetAttribute(flash_kernel,
                         cudaFuncAttributeMaxDynamicSharedMemorySize,
                         FLASH_SMEM_BYTES);

    // 0. weights -> bf16
    f2bf_kernel<<<(3 * DD * DD / 4 + 255) / 256, 256>>>(qkv_w, p_wqkv, 3 * DD * DD / 4);
    f2bf_kernel<<<(DD * DD / 4 + 255) / 256, 256>>>(out_w, p_wout, DD * DD / 4);
    // 1. RMSNorm (bf16 out)
    rmsnorm_kernel<<<ROWS, 256>>>(x, norm_w);
    // 2. QKV projection (mma.sync bf16): [8192,3072] = xn @ qkv_w^T
    gemm_mma<false><<<dim3((3 * DD) / 128, ROWS / 128), 256>>>(
        p_xn, p_wqkv, p_qkv, 3 * DD, DD, nullptr, nullptr);
    // 3. RoPE + scatter to [B,H,L,hd]
    rope_scatter_kernel<<<(ROWS * 1536) / 256, 256>>>();
    // 4. attention (fp32)
    flash_kernel<<<dim3(LL / 64, BHN), 256, FLASH_SMEM_BYTES>>>();
    // 5. out projection + residual epilogue (mma.sync bf16) -> d_out
    gemm_mma<true><<<dim3(DD / 128, ROWS / 128), 256>>>(
        p_ao, p_wout, out, DD, DD, x, rsp);
}